// round 8
// baseline (speedup 1.0000x reference)
#include <cuda_runtime.h>
#include <cstdint>

#define NB 64
#define C  128
#define H  56
#define W  56
#define HW 3136
#define PROW 58
#define PIMG 3364                     // 58*58
#define IMG_ROWS 3584                 // 3364 data rows + 220 zero tail
#define GUARD 128
#define TOT_ROWS (GUARD + NB*IMG_ROWS)
#define TPI 27                        // ceil(3364/128) M-tiles per image
#define NT (NB*TPI)                   // 1728
#define GRID_CONV 144
#define TILES_PER_CTA 12              // 144*12 = 1728
#define ROWB 144                      // padded smem row stride (bank-friendly, 16B aligned)

// smem layout (dynamic)
#define SM_B   0
#define BT     (128*ROWB)             // 18432 per tap
#define SM_A   (9*BT)                 // 165888
#define SM_AF  (SM_A + 246*ROWB)     // 201312
#define SM_BF  (SM_AF + 512)
#define SMEM_TOTAL (SM_BF + 512)      // 202336

__device__ __align__(1024) unsigned char g_spad[(size_t)TOT_ROWS * 128]; // s8 signs, padded linear NHWC (k-permuted)
__device__ __align__(16)   unsigned char g_bs8[9 * 128 * 128];           // [tap][co][ci'] s8 signs (k-permuted)
__device__ float g_A[C], g_Bc[C];

// k-word permutation within each 32-byte chunk: [0,4,1,5,2,6,3,7].
// Applied identically to A and B rows -> dot products unchanged, and each
// mma fragment pair (logical words w, w+4) becomes adjacent -> ld.shared.v2.
__host__ __device__ __forceinline__ int permw(int w) {
    int ww = w & 7;
    return (w & ~7) | ((ww < 4) ? (ww << 1) : (((ww - 4) << 1) | 1));
}

__device__ __forceinline__ uint32_t smem_u32(const void* p) {
    uint32_t a;
    asm("{ .reg .u64 t; cvta.to.shared.u64 t, %1; cvt.u32.u64 %0, t; }" : "=r"(a) : "l"(p));
    return a;
}

// ---------------- Kernel 0: zero the padded s8 buffer ----------------
__global__ void zero_kernel() {
    size_t i = (size_t)blockIdx.x * blockDim.x + threadIdx.x;
    size_t n4 = (size_t)TOT_ROWS * 128 / 16;
    if (i < n4) reinterpret_cast<uint4*>(g_spad)[i] = make_uint4(0u, 0u, 0u, 0u);
}

// ---------------- Kernel 1: signs -> padded NHWC s8 (+1/-1), k-permuted ----------------
__global__ void sign_kernel(const float* __restrict__ x) {
    __shared__ uint32_t s[56][33];     // pad 33 words -> conflict-free both phases
    int nb = blockIdx.x;
    int n = nb / H, h = nb - n * H;
    int t = threadIdx.x;
    const float* xp = x + (size_t)n * C * HW + (size_t)h * W;
    for (int it = t; it < 56 * 32; it += 256) {
        int w = it % 56, cg = it / 56;           // cg = ci word (4 channels)
        uint32_t b = 0;
#pragma unroll
        for (int j = 0; j < 4; j++) {
            float v = __ldg(xp + (size_t)(cg * 4 + j) * HW + w);
            b |= ((v < 0.0f) ? 0xFFu : 0x01u) << (j * 8);   // s8 -1 / +1
        }
        s[w][cg] = b;
    }
    __syncthreads();
    uint32_t* dst = (uint32_t*)(g_spad +
        ((size_t)GUARD + (size_t)n * IMG_ROWS + (size_t)(h + 1) * PROW + 1) * 128);
    for (int it = t; it < 56 * 32; it += 256) {
        int pix = it >> 5, l = it & 31;
        dst[(size_t)pix * 32 + permw(l)] = s[pix][l];
    }
}

// ---------------- Kernel 2: weight prep -> s8 signs (k-permuted) + per-co affine ----------------
__global__ void wprep_kernel(const float* __restrict__ wgt,
                             const float* __restrict__ gamma,
                             const float* __restrict__ beta,
                             const float* __restrict__ mean,
                             const float* __restrict__ var) {
    int tid = threadIdx.x;            // 0..511
    int co = tid >> 2, q = tid & 3;
    const float* wp = wgt + (size_t)co * 1152;
    float sabs = 0.0f;
    for (int cb = 0; cb < 32; cb++) {
        int ci = q * 32 + cb;
        int pci = permw(ci >> 2) * 4 + (ci & 3);
#pragma unroll
        for (int tap = 0; tap < 9; tap++) {
            float v = wp[ci * 9 + tap];
            sabs += fabsf(v);
            g_bs8[((size_t)tap * 128 + co) * 128 + pci] = (v < 0.0f) ? 0xFF : 0x01;
        }
    }
    sabs += __shfl_xor_sync(0xffffffffu, sabs, 1);
    sabs += __shfl_xor_sync(0xffffffffu, sabs, 2);
    if (q == 0) {
        float scale = sabs * (1.0f / 1152.0f);
        float inv = gamma[co] * rsqrtf(var[co] + 1e-5f);
        g_A[co]  = scale * inv;
        g_Bc[co] = beta[co] - mean[co] * inv;
    }
}

// ---------------- Kernel 3: persistent s8 mma.sync implicit-GEMM conv ----------------
// CTA tile: M=128 padded pixels x N=128 co, K = 9 taps x 128 ci.
// 8 warps: warp_m = warp>>1 (m0 = 32*warp_m), warp_n = warp&1 (n0 = 64*warp_n).
// Warp tile 32x64 = 2 m-tiles x 8 n-tiles of m16n8k32.
__global__ void __launch_bounds__(256, 1)
conv_kernel(const float* __restrict__ x, float* __restrict__ out) {
    extern __shared__ unsigned char smem[];
    const int tid  = threadIdx.x;
    const int warp = tid >> 5;
    const int lane = tid & 31;
    const int g  = lane >> 2;
    const int tg = lane & 3;
    const int m0 = (warp >> 1) * 32;
    const int n0 = (warp & 1) * 64;
    const uint32_t sb = smem_u32(smem);

    // stage B: 1152 rows x 128 B -> padded 144-B rows (already k-permuted at source)
    for (int i = tid; i < 1152 * 8; i += 256) {
        int r = i >> 3, j = i & 7;
        *(uint4*)(smem + SM_B + r * ROWB + j * 16) =
            ((const uint4*)(g_bs8 + (size_t)r * 128))[j];
    }
    if (tid < C) {
        ((float*)(smem + SM_AF))[tid] = g_A[tid];
        ((float*)(smem + SM_BF))[tid] = g_Bc[tid];
    }
    __syncthreads();

    // preload per-lane BN scales (co set fixed per lane across all tiles)
    float rA[16], rB[16];
#pragma unroll
    for (int ni = 0; ni < 8; ni++) {
        int co = n0 + ni * 8 + tg * 2;
        rA[ni * 2]     = ((const float*)(smem + SM_AF))[co];
        rA[ni * 2 + 1] = ((const float*)(smem + SM_AF))[co + 1];
        rB[ni * 2]     = ((const float*)(smem + SM_BF))[co];
        rB[ni * 2 + 1] = ((const float*)(smem + SM_BF))[co + 1];
    }

    const uint32_t aAddr = sb + SM_A + (uint32_t)(m0 + g) * ROWB + tg * 8;
    const uint32_t bAddr = sb + SM_B + (uint32_t)(n0 + g) * ROWB + tg * 8;

    for (int it = 0; it < TILES_PER_CTA; it++) {
        int t   = blockIdx.x * TILES_PER_CTA + it;
        int img = t / TPI, tt = t - img * TPI;
        size_t row0 = (size_t)GUARD + (size_t)img * IMG_ROWS + (size_t)tt * 128 - 59;

        // stage A span: 246 rows x 128 B -> 144-B padded rows
        for (int i = tid; i < 246 * 8; i += 256) {
            int r = i >> 3, j = i & 7;
            *(uint4*)(smem + SM_A + r * ROWB + j * 16) =
                ((const uint4*)(g_spad + (row0 + r) * 128))[j];
        }
        __syncthreads();

        int c[2][8][4];
#pragma unroll
        for (int mi = 0; mi < 2; mi++)
#pragma unroll
            for (int ni = 0; ni < 8; ni++)
#pragma unroll
                for (int r = 0; r < 4; r++) c[mi][ni][r] = 0;

        for (int tap = 0; tap < 9; tap++) {
            const int tapoff = (tap / 3) * 58 + (tap % 3);
            const uint32_t at = aAddr + (uint32_t)tapoff * ROWB;
            const uint32_t bt = bAddr + (uint32_t)tap * BT;
#pragma unroll
            for (int ks = 0; ks < 4; ks++) {
                uint32_t a[2][4];
#pragma unroll
                for (int mi = 0; mi < 2; mi++) {
                    uint32_t lo = at + mi * (16 * ROWB) + ks * 32;
                    asm volatile("ld.shared.v2.b32 {%0,%1}, [%2];"
                                 : "=r"(a[mi][0]), "=r"(a[mi][2]) : "r"(lo));
                    asm volatile("ld.shared.v2.b32 {%0,%1}, [%2];"
                                 : "=r"(a[mi][1]), "=r"(a[mi][3]) : "r"(lo + 8 * ROWB));
                }
#pragma unroll
                for (int ni = 0; ni < 8; ni++) {
                    uint32_t b0, b1;
                    asm volatile("ld.shared.v2.b32 {%0,%1}, [%2];"
                                 : "=r"(b0), "=r"(b1)
                                 : "r"(bt + ni * (8 * ROWB) + ks * 32));
#pragma unroll
                    for (int mi = 0; mi < 2; mi++) {
                        asm volatile(
                            "mma.sync.aligned.m16n8k32.row.col.s32.s8.s8.s32 "
                            "{%0,%1,%2,%3}, {%4,%5,%6,%7}, {%8,%9}, {%0,%1,%2,%3};"
                            : "+r"(c[mi][ni][0]), "+r"(c[mi][ni][1]),
                              "+r"(c[mi][ni][2]), "+r"(c[mi][ni][3])
                            : "r"(a[mi][0]), "r"(a[mi][1]), "r"(a[mi][2]), "r"(a[mi][3]),
                              "r"(b0), "r"(b1));
                    }
                }
            }
        }

        // epilogue: c[mi][ni][{0,1}] rows g / [{2,3}] rows g+8; cols tg*2 + {0,1}
        size_t base = (size_t)img * C * HW;
#pragma unroll
        for (int mi = 0; mi < 2; mi++) {
#pragma unroll
            for (int half = 0; half < 2; half++) {
                int row  = m0 + mi * 16 + half * 8 + g;
                int pos  = tt * 128 + row;
                int prow = pos / PROW;
                int pcol = pos - prow * PROW;
                bool valid = (pos < PIMG) && (prow >= 1) && (prow <= 56)
                          && (pcol >= 1) && (pcol <= 56);
                if (valid) {
                    size_t off = base + (size_t)(prow - 1) * W + (pcol - 1);
#pragma unroll
                    for (int ni = 0; ni < 8; ni++) {
                        int co = n0 + ni * 8 + tg * 2;
                        size_t o0 = off + (size_t)co * HW;
                        float r0 = __ldg(x + o0);
                        float r1 = __ldg(x + o0 + HW);
                        out[o0] = fmaf((float)c[mi][ni][half * 2],
                                       rA[ni * 2], rB[ni * 2]) + r0;
                        out[o0 + HW] = fmaf((float)c[mi][ni][half * 2 + 1],
                                            rA[ni * 2 + 1], rB[ni * 2 + 1]) + r1;
                    }
                }
            }
        }
        __syncthreads();   // all smem reads done before next tile's staging
    }
}

// ---------------------------------------------------------------------------
extern "C" void kernel_launch(void* const* d_in, const int* in_sizes, int n_in,
                              void* d_out, int out_size) {
    const float* x     = (const float*)d_in[0];
    const float* wgt   = (const float*)d_in[1];
    const float* gamma = (const float*)d_in[2];
    const float* beta  = (const float*)d_in[3];
    const float* mean  = (const float*)d_in[4];
    const float* var   = (const float*)d_in[5];
    float* out = (float*)d_out;
    (void)in_sizes; (void)n_in; (void)out_size;

    cudaFuncSetAttribute(conv_kernel, cudaFuncAttributeMaxDynamicSharedMemorySize, SMEM_TOTAL);

    size_t n4 = (size_t)TOT_ROWS * 128 / 16;
    zero_kernel<<<(int)((n4 + 255) / 256), 256>>>();
    sign_kernel<<<NB * H, 256>>>(x);
    wprep_kernel<<<1, 512>>>(wgt, gamma, beta, mean, var);
    conv_kernel<<<GRID_CONV, 256, SMEM_TOTAL>>>(x, out);
}

// round 9
// speedup vs baseline: 1.6574x; 1.6574x over previous
#include <cuda_runtime.h>
#include <cstdint>

#define NB 64
#define C  128
#define H  56
#define W  56
#define HW 3136
#define PROW 58
#define PIMG 3364
#define IMG_ROWS 3584
#define GUARD 128
#define TOT_ROWS (GUARD + NB*IMG_ROWS)
#define TPI 27
#define NTT (NB*TPI)                  // 1728 tensor tiles
#define NPAIR (NB*28)                 // 1792 scalar row-pairs
#define GRID_CONV 148
#define ROWB 144
#define NCT 40                        // tensor co count (co 0..39)
#define NCS 88                        // scalar co count (co 40..127)

// smem offsets (bytes)
#define SM_B   0                      // 9*40*ROWB = 51840
#define SM_A   51840                  // 246*ROWB = 35424
#define SM_W   87264                  // 88*9*16 = 12672
#define SM_X   99936                  // 4*58*16 = 3712
#define SM_CC  103648                 // 3*88*16 = 4224
#define SM_Q2  107872                 // 3*88*4 = 1056
#define SM_ABN 108928                 // 40*2*4 = 320
#define SMEM_TOTAL 109248

__device__ __align__(1024) unsigned char g_spad[(size_t)TOT_ROWS * 128]; // s8 signs, k-permuted
__device__ __align__(16)   unsigned char g_bs8[9 * NCT * 128];           // [tap][co<40][ci'] s8
__device__ __align__(16)   uint32_t g_wbits[C * 9 * 4];                  // bitmask [co][tap][word]
__device__ float g_A[C], g_Bc[C], g_wcnt[C * 9];
__device__ uint4 g_xbits[NB * HW];

__host__ __device__ __forceinline__ int permw(int w) {
    int ww = w & 7;
    return (w & ~7) | ((ww < 4) ? (ww << 1) : (((ww - 4) << 1) | 1));
}
__device__ __forceinline__ uint32_t smem_u32(const void* p) {
    uint32_t a;
    asm("{ .reg .u64 t; cvta.to.shared.u64 t, %1; cvt.u32.u64 %0, t; }" : "=r"(a) : "l"(p));
    return a;
}
__device__ __forceinline__ void fadd(uint32_t a, uint32_t b, uint32_t c,
                                     uint32_t& s, uint32_t& cy) {
    s = a ^ b ^ c; cy = (a & b) | (c & (a ^ b));
}

// ---------------- Kernel 0: zero spad ----------------
__global__ void zero_kernel() {
    size_t i = (size_t)blockIdx.x * blockDim.x + threadIdx.x;
    size_t n4 = (size_t)TOT_ROWS * 128 / 16;
    if (i < n4) reinterpret_cast<uint4*>(g_spad)[i] = make_uint4(0u, 0u, 0u, 0u);
}

// ---------------- Kernel 1: x -> s8 spad (permuted) + bitpacked xbits ----------------
__global__ void sign_kernel(const float* __restrict__ x) {
    __shared__ uint32_t s[56][33];
    int nb = blockIdx.x;
    int n = nb / H, h = nb - n * H;
    int t = threadIdx.x;
    const float* xp = x + (size_t)n * C * HW + (size_t)h * W;
    for (int it = t; it < 56 * 32; it += 256) {
        int w = it % 56, cg = it / 56;
        uint32_t b = 0;
#pragma unroll
        for (int j = 0; j < 4; j++) {
            float v = __ldg(xp + (size_t)(cg * 4 + j) * HW + w);
            b |= ((v < 0.0f) ? 0xFFu : 0x01u) << (j * 8);
        }
        s[w][cg] = b;
    }
    __syncthreads();
    uint32_t* dst = (uint32_t*)(g_spad +
        ((size_t)GUARD + (size_t)n * IMG_ROWS + (size_t)(h + 1) * PROW + 1) * 128);
    for (int it = t; it < 56 * 32; it += 256) {
        int pix = it >> 5, l = it & 31;
        dst[(size_t)pix * 32 + permw(l)] = s[pix][l];
    }
    // bitpack: thread (w, j): 32 sign bits from 8 s-words
    if (t < 224) {
        int w = t >> 2, j = t & 3;
        uint32_t b = 0;
#pragma unroll
        for (int m = 0; m < 8; m++) {
            uint32_t sv = s[w][j * 8 + m];
#pragma unroll
            for (int k = 0; k < 4; k++)
                b |= ((sv >> (8 * k + 7)) & 1u) << (m * 4 + k);
        }
        ((uint32_t*)&g_xbits[(size_t)n * HW + h * W + w])[j] = b;
    }
}

// ---------------- Kernel 2: weight prep ----------------
__global__ void wprep_kernel(const float* __restrict__ wgt,
                             const float* __restrict__ gamma,
                             const float* __restrict__ beta,
                             const float* __restrict__ mean,
                             const float* __restrict__ var) {
    int tid = threadIdx.x;            // 0..511
    int co = tid >> 2, j = tid & 3;
    const float* wp = wgt + (size_t)co * 1152;
    uint32_t wb[9];
#pragma unroll
    for (int t = 0; t < 9; t++) wb[t] = 0;
    float sabs = 0.0f;
    for (int c = 0; c < 32; c++) {
        int ci = j * 32 + c;
        int pci = permw(ci >> 2) * 4 + (ci & 3);
#pragma unroll
        for (int t = 0; t < 9; t++) {
            float v = wp[ci * 9 + t];
            sabs += fabsf(v);
            wb[t] |= (uint32_t)(__float_as_uint(v) >> 31) << c;
            if (co < NCT)
                g_bs8[((size_t)t * NCT + co) * 128 + pci] = (v < 0.0f) ? 0xFF : 0x01;
        }
    }
    sabs += __shfl_xor_sync(0xffffffffu, sabs, 1);
    sabs += __shfl_xor_sync(0xffffffffu, sabs, 2);
#pragma unroll
    for (int t = 0; t < 9; t++) {
        g_wbits[(co * 9 + t) * 4 + j] = wb[t];
        int pc = __popc(wb[t]);
        pc += __shfl_xor_sync(0xffffffffu, pc, 1);
        pc += __shfl_xor_sync(0xffffffffu, pc, 2);
        if (j == 0) g_wcnt[co * 9 + t] = (float)pc;
    }
    if (j == 0) {
        float scale = sabs * (1.0f / 1152.0f);
        float inv = gamma[co] * rsqrtf(var[co] + 1e-5f);
        g_A[co] = scale * inv;
        g_Bc[co] = beta[co] - mean[co] * inv;
    }
}

// ---------------- Kernel 3: hybrid conv (tensor co 0..39, scalar co 40..127) ----------------
__global__ void __launch_bounds__(512, 1)
conv_kernel(const float* __restrict__ x, float* __restrict__ out) {
    extern __shared__ unsigned char smem[];
    const int tid = threadIdx.x;
    const int warp = tid >> 5;
    const int lane = tid & 31;
    const int cta = blockIdx.x;
    const uint32_t sb = smem_u32(smem);

    // ---- shared staging (all 512 threads) ----
    for (int i = tid; i < 9 * NCT * 8; i += 512) {      // B s8 tiles
        int r = i >> 3, j = i & 7;
        *(uint4*)(smem + SM_B + r * ROWB + j * 16) = ((const uint4*)(g_bs8 + (size_t)r * 128))[j];
    }
    {
        const uint4* gw = (const uint4*)g_wbits;
        for (int i = tid; i < NCS * 9; i += 512)        // scalar weight bitmasks (co>=40)
            ((uint4*)(smem + SM_W))[i] = gw[NCT * 9 + i];
    }
    for (int i = tid; i < 3 * NCS; i += 512) {          // scalar epilogue consts, 3 h-classes
        int cl = i / NCS, co = NCT + (i - cl * NCS);
        float A = g_A[co], Bv = g_Bc[co];
        float wc[9];
#pragma unroll
        for (int t = 0; t < 9; t++) wc[t] = g_wcnt[co * 9 + t];
        float cr = (cl == 0 ? wc[0] + wc[1] + wc[2] : 0.0f)
                 + (cl == 2 ? wc[6] + wc[7] + wc[8] : 0.0f);
        float c0 = (cl == 0 ? 0.0f : wc[0]) + wc[3] + (cl == 2 ? 0.0f : wc[6]);
        float c2 = (cl == 0 ? 0.0f : wc[2]) + wc[5] + (cl == 2 ? 0.0f : wc[8]);
        ((float4*)(smem + SM_CC))[i] = make_float4(-2.0f * A, A, fmaf(2.0f * A, cr, Bv), 2.0f * A * c0);
        ((float*)(smem + SM_Q2))[i] = 2.0f * A * c2;
    }
    if (tid < NCT) {
        ((float*)(smem + SM_ABN))[tid] = g_A[tid];
        ((float*)(smem + SM_ABN))[NCT + tid] = g_Bc[tid];
    }
    __syncthreads();

    if (warp < 4) {
        // ================= TENSOR GROUP: 4 warps, co 0..39 =================
        const int g = lane >> 2, tg = lane & 3;
        const int m0 = warp * 32;
        const int t0 = (int)(((long)cta * NTT) / GRID_CONV);
        const int t1 = (int)(((long)(cta + 1) * NTT) / GRID_CONV);
        const uint32_t aAddr = sb + SM_A + (uint32_t)(m0 + g) * ROWB + tg * 8;
        const uint32_t bAddr = sb + SM_B + (uint32_t)g * ROWB + tg * 8;
        const float* abn = (const float*)(smem + SM_ABN);

        for (int t = t0; t < t1; t++) {
            int img = t / TPI, tt = t - img * TPI;
            size_t row0 = (size_t)GUARD + (size_t)img * IMG_ROWS + (size_t)tt * 128 - 59;
            for (int i = tid; i < 246 * 8; i += 128) {
                int r = i >> 3, j = i & 7;
                *(uint4*)(smem + SM_A + r * ROWB + j * 16) =
                    ((const uint4*)(g_spad + (row0 + r) * 128))[j];
            }
            asm volatile("bar.sync 1, 128;" ::: "memory");

            int c[2][5][4];
#pragma unroll
            for (int mi = 0; mi < 2; mi++)
#pragma unroll
                for (int ni = 0; ni < 5; ni++)
#pragma unroll
                    for (int r = 0; r < 4; r++) c[mi][ni][r] = 0;

            for (int tap = 0; tap < 9; tap++) {
                const uint32_t at = aAddr + (uint32_t)((tap / 3) * 58 + (tap % 3)) * ROWB;
                const uint32_t bt = bAddr + (uint32_t)(tap * NCT) * ROWB;
#pragma unroll
                for (int ks = 0; ks < 4; ks++) {
                    uint32_t a[2][4];
#pragma unroll
                    for (int mi = 0; mi < 2; mi++) {
                        uint32_t lo = at + mi * (16 * ROWB) + ks * 32;
                        asm volatile("ld.shared.v2.b32 {%0,%1}, [%2];"
                                     : "=r"(a[mi][0]), "=r"(a[mi][2]) : "r"(lo));
                        asm volatile("ld.shared.v2.b32 {%0,%1}, [%2];"
                                     : "=r"(a[mi][1]), "=r"(a[mi][3]) : "r"(lo + 8 * ROWB));
                    }
#pragma unroll
                    for (int ni = 0; ni < 5; ni++) {
                        uint32_t b0, b1;
                        asm volatile("ld.shared.v2.b32 {%0,%1}, [%2];"
                                     : "=r"(b0), "=r"(b1) : "r"(bt + ni * (8 * ROWB) + ks * 32));
#pragma unroll
                        for (int mi = 0; mi < 2; mi++) {
                            asm volatile(
                                "mma.sync.aligned.m16n8k32.row.col.s32.s8.s8.s32 "
                                "{%0,%1,%2,%3}, {%4,%5,%6,%7}, {%8,%9}, {%0,%1,%2,%3};"
                                : "+r"(c[mi][ni][0]), "+r"(c[mi][ni][1]),
                                  "+r"(c[mi][ni][2]), "+r"(c[mi][ni][3])
                                : "r"(a[mi][0]), "r"(a[mi][1]), "r"(a[mi][2]), "r"(a[mi][3]),
                                  "r"(b0), "r"(b1));
                        }
                    }
                }
            }
            size_t base = (size_t)img * C * HW;
#pragma unroll
            for (int mi = 0; mi < 2; mi++) {
#pragma unroll
                for (int half = 0; half < 2; half++) {
                    int row = m0 + mi * 16 + half * 8 + g;
                    int pos = tt * 128 + row;
                    int prow = pos / PROW, pcol = pos - prow * PROW;
                    if (pos < PIMG && prow >= 1 && prow <= 56 && pcol >= 1 && pcol <= 56) {
                        size_t off = base + (size_t)(prow - 1) * W + (pcol - 1);
#pragma unroll
                        for (int ni = 0; ni < 5; ni++) {
                            int co = ni * 8 + tg * 2;
                            size_t o0 = off + (size_t)co * HW;
                            float r0 = __ldg(x + o0), r1 = __ldg(x + o0 + HW);
                            out[o0] = fmaf((float)c[mi][ni][half * 2], abn[co], abn[NCT + co]) + r0;
                            out[o0 + HW] = fmaf((float)c[mi][ni][half * 2 + 1], abn[co + 1], abn[NCT + co + 1]) + r1;
                        }
                    }
                }
            }
            asm volatile("bar.sync 1, 128;" ::: "memory");
        }
    } else {
        // ================= SCALAR GROUP: 12 warps, co 40..127 =================
        const int sw = warp - 4;                // 0..11
        const int rowsel = sw & 1;
        const int grp = sw >> 1;                // 0..5
        const int half = grp & 1;
        const int chunk = grp >> 1;             // 0..2
        const int co_cnt = (chunk == 2) ? 28 : 30;
        const int co0 = NCT + chunk * 30;
        const int stid = tid - 128;             // 0..383
        int w = half * 32 + lane;
        bool wok = (w < 56);
        int wc_ = wok ? w : 0;

        const int p0 = (int)(((long)cta * NPAIR) / GRID_CONV);
        const int p1 = (int)(((long)(cta + 1) * NPAIR) / GRID_CONV);
        uint4* s_x = (uint4*)(smem + SM_X);
        const uint4* s_w = (const uint4*)(smem + SM_W);
        const float4* s_cc = (const float4*)(smem + SM_CC);
        const float* s_q2 = (const float*)(smem + SM_Q2);

        for (int p = p0; p < p1; p++) {
            int img = p / 28, pr = p - img * 28;
            int hbase = pr * 2;
            asm volatile("bar.sync 2, 384;" ::: "memory");
            // stage 4 xbit rows hbase-1 .. hbase+2, zero-padded
            for (int i = stid; i < 4 * 58; i += 384) {
                int r = i / 58, cw = i - r * 58 - 1;
                int hr = hbase - 1 + r;
                uint4 v = make_uint4(0u, 0u, 0u, 0u);
                if (hr >= 0 && hr < 56 && cw >= 0 && cw < 56)
                    v = g_xbits[(size_t)img * HW + hr * W + cw];
                s_x[i] = v;
            }
            asm volatile("bar.sync 2, 384;" ::: "memory");

            int h = hbase + rowsel;
            int cl = (h == 0) ? 0 : ((h == 55) ? 2 : 1);
            float q0f = (w == 0) ? 1.0f : 0.0f;
            float q2f = (w == 55) ? 1.0f : 0.0f;
            float vr = 3.0f - (cl == 0 ? 1.0f : 0.0f) - (cl == 2 ? 1.0f : 0.0f);
            float nv128 = 128.0f * vr * (3.0f - q0f - q2f);

            uint4 xv[9];
#pragma unroll
            for (int t = 0; t < 9; t++)
                xv[t] = s_x[(rowsel + t / 3) * 58 + wc_ + (t % 3)];

            const float* resid = x + (size_t)img * C * HW + (size_t)h * W + wc_;
            float* outp = out + (size_t)img * C * HW + (size_t)h * W + wc_;

#pragma unroll 2
            for (int k = 0; k < co_cnt; k++) {
                int co = co0 + k;
                int ic = co - NCT;
                float r = resid[(size_t)co * HW];
                float4 cf = s_cc[cl * NCS + ic];
                float q2v = s_q2[cl * NCS + ic];
                int acc1 = 0, acc2 = 0;
#pragma unroll
                for (int g2 = 0; g2 < 3; g2++) {
                    uint4 wv0 = s_w[ic * 9 + 3 * g2 + 0];
                    uint4 wv1 = s_w[ic * 9 + 3 * g2 + 1];
                    uint4 wv2 = s_w[ic * 9 + 3 * g2 + 2];
                    uint32_t s0, c0, s1, c1, s2, c2, s3, c3;
                    fadd(xv[3*g2].x ^ wv0.x, xv[3*g2+1].x ^ wv1.x, xv[3*g2+2].x ^ wv2.x, s0, c0);
                    fadd(xv[3*g2].y ^ wv0.y, xv[3*g2+1].y ^ wv1.y, xv[3*g2+2].y ^ wv2.y, s1, c1);
                    fadd(xv[3*g2].z ^ wv0.z, xv[3*g2+1].z ^ wv1.z, xv[3*g2+2].z ^ wv2.z, s2, c2);
                    fadd(xv[3*g2].w ^ wv0.w, xv[3*g2+1].w ^ wv1.w, xv[3*g2+2].w ^ wv2.w, s3, c3);
                    acc1 += __popc(s0) + __popc(s1) + __popc(s2) + __popc(s3);
                    acc2 += __popc(c0) + __popc(c1) + __popc(c2) + __popc(c3);
                }
                int acc = acc1 + 2 * acc2;
                float K = fmaf(cf.y, nv128, cf.z);
                K = fmaf(q0f, cf.w, K);
                K = fmaf(q2f, q2v, K);
                if (wok) outp[(size_t)co * HW] = fmaf(cf.x, (float)acc, K) + r;
            }
        }
    }
}

// ---------------------------------------------------------------------------
extern "C" void kernel_launch(void* const* d_in, const int* in_sizes, int n_in,
                              void* d_out, int out_size) {
    const float* x     = (const float*)d_in[0];
    const float* wgt   = (const float*)d_in[1];
    const float* gamma = (const float*)d_in[2];
    const float* beta  = (const float*)d_in[3];
    const float* mean  = (const float*)d_in[4];
    const float* var   = (const float*)d_in[5];
    float* out = (float*)d_out;
    (void)in_sizes; (void)n_in; (void)out_size;

    cudaFuncSetAttribute(conv_kernel, cudaFuncAttributeMaxDynamicSharedMemorySize, SMEM_TOTAL);

    size_t n4 = (size_t)TOT_ROWS * 128 / 16;
    zero_kernel<<<(int)((n4 + 255) / 256), 256>>>();
    sign_kernel<<<NB * H, 256>>>(x);
    wprep_kernel<<<1, 512>>>(wgt, gamma, beta, mean, var);
    conv_kernel<<<GRID_CONV, 512, SMEM_TOTAL>>>(x, out);
}

// round 10
// speedup vs baseline: 2.1154x; 1.2763x over previous
#include <cuda_runtime.h>
#include <cstdint>

#define NB 64
#define C  128
#define H  56
#define W  56
#define HW 3136
#define PROW 58
#define PIMG 3364
#define IMG_ROWS 3584
#define GUARD 128
#define TOT_ROWS (GUARD + NB*IMG_ROWS)
#define TPI 27
#define NTT (NB*TPI)                  // 1728 tensor tiles
#define NPAIR (NB*28)                 // 1792 scalar row-pairs
#define GRID_CONV 148
#define ROWB 144
#define NCT 40                        // tensor co count (co 0..39)
#define NCS 88                        // scalar co count (co 40..127)

// smem offsets (bytes)
#define SM_B   0                      // 9*40*ROWB = 51840
#define SM_A   51840                  // 246*ROWB = 35424
#define SM_W   87264                  // 88*9*16 = 12672
#define SM_X   99936                  // 4*58*16 = 3712
#define SM_CC  103648                 // 3*88*16 = 4224
#define SM_Q2  107872                 // 3*88*4 = 1056
#define SM_ABN 108928                 // 40*2*4 = 320
#define SMEM_TOTAL 109248

// NOTE: no zero_kernel — static __device__ globals are zero-initialized at
// module load, and interior writes below never touch pad/guard/tail rows.
__device__ __align__(1024) unsigned char g_spad[(size_t)TOT_ROWS * 128]; // s8 signs, k-permuted
__device__ __align__(16)   unsigned char g_bs8[9 * NCT * 128];           // [tap][co<40][ci'] s8
__device__ __align__(16)   uint32_t g_wbits[C * 9 * 4];                  // bitmask [co][tap][word]
__device__ float g_A[C], g_Bc[C], g_wcnt[C * 9];
__device__ uint4 g_xbits[NB * HW];

__host__ __device__ __forceinline__ int permw(int w) {
    int ww = w & 7;
    return (w & ~7) | ((ww < 4) ? (ww << 1) : (((ww - 4) << 1) | 1));
}
__device__ __forceinline__ uint32_t smem_u32(const void* p) {
    uint32_t a;
    asm("{ .reg .u64 t; cvta.to.shared.u64 t, %1; cvt.u32.u64 %0, t; }" : "=r"(a) : "l"(p));
    return a;
}
__device__ __forceinline__ void fadd(uint32_t a, uint32_t b, uint32_t c,
                                     uint32_t& s, uint32_t& cy) {
    s = a ^ b ^ c; cy = (a & b) | (c & (a ^ b));
}

// ---------------- Kernel 1: x -> s8 spad (permuted) + bitpacked xbits ----------------
__global__ void sign_kernel(const float* __restrict__ x) {
    __shared__ uint32_t s[56][33];
    int nb = blockIdx.x;
    int n = nb / H, h = nb - n * H;
    int t = threadIdx.x;
    const float* xp = x + (size_t)n * C * HW + (size_t)h * W;
    for (int it = t; it < 56 * 32; it += 256) {
        int w = it % 56, cg = it / 56;
        uint32_t b = 0;
#pragma unroll
        for (int j = 0; j < 4; j++) {
            float v = __ldg(xp + (size_t)(cg * 4 + j) * HW + w);
            b |= ((v < 0.0f) ? 0xFFu : 0x01u) << (j * 8);
        }
        s[w][cg] = b;
    }
    __syncthreads();
    uint32_t* dst = (uint32_t*)(g_spad +
        ((size_t)GUARD + (size_t)n * IMG_ROWS + (size_t)(h + 1) * PROW + 1) * 128);
    for (int it = t; it < 56 * 32; it += 256) {
        int pix = it >> 5, l = it & 31;
        dst[(size_t)pix * 32 + permw(l)] = s[pix][l];
    }
    if (t < 224) {
        int w = t >> 2, j = t & 3;
        uint32_t b = 0;
#pragma unroll
        for (int m = 0; m < 8; m++) {
            uint32_t sv = s[w][j * 8 + m];
#pragma unroll
            for (int k = 0; k < 4; k++)
                b |= ((sv >> (8 * k + 7)) & 1u) << (m * 4 + k);
        }
        ((uint32_t*)&g_xbits[(size_t)n * HW + h * W + w])[j] = b;
    }
}

// ---------------- Kernel 2: parallel weight prep (grid = 128 co, 128 thr) ----------------
__global__ void wprep_kernel(const float* __restrict__ wgt,
                             const float* __restrict__ gamma,
                             const float* __restrict__ beta,
                             const float* __restrict__ mean,
                             const float* __restrict__ var) {
    __shared__ float s_abs[4];
    __shared__ int   s_pc[9][4];
    int co = blockIdx.x;
    int t  = threadIdx.x;          // = ci
    int lane = t & 31, j = t >> 5;

    float v[9];
    const float* wp = wgt + (size_t)co * 1152 + (size_t)t * 9;
    float sabs = 0.0f;
#pragma unroll
    for (int tap = 0; tap < 9; tap++) { v[tap] = wp[tap]; sabs += fabsf(v[tap]); }
#pragma unroll
    for (int o = 16; o > 0; o >>= 1) sabs += __shfl_xor_sync(0xffffffffu, sabs, o);
    if (lane == 0) s_abs[j] = sabs;

    int pci = permw(t >> 2) * 4 + (t & 3);
#pragma unroll
    for (int tap = 0; tap < 9; tap++) {
        uint32_t wb = __ballot_sync(0xffffffffu, v[tap] < 0.0f);
        if (lane == 0) {
            g_wbits[(co * 9 + tap) * 4 + j] = wb;
            s_pc[tap][j] = __popc(wb);
        }
        if (co < NCT)
            g_bs8[((size_t)tap * NCT + co) * 128 + pci] = (v[tap] < 0.0f) ? 0xFF : 0x01;
    }
    __syncthreads();
    if (t < 9)
        g_wcnt[co * 9 + t] = (float)(s_pc[t][0] + s_pc[t][1] + s_pc[t][2] + s_pc[t][3]);
    if (t == 0) {
        float tot = s_abs[0] + s_abs[1] + s_abs[2] + s_abs[3];
        float scale = tot * (1.0f / 1152.0f);
        float inv = gamma[co] * rsqrtf(var[co] + 1e-5f);
        g_A[co]  = scale * inv;
        g_Bc[co] = beta[co] - mean[co] * inv;
    }
}

// ---------------- Kernel 3: hybrid conv (tensor co 0..39, scalar co 40..127) ----------------
// 576 threads: warps 0-3 tensor (mma.sync), warps 4-17 scalar (CSA popcount).
__global__ void __launch_bounds__(576, 1)
conv_kernel(const float* __restrict__ x, float* __restrict__ out) {
    extern __shared__ unsigned char smem[];
    const int tid = threadIdx.x;
    const int warp = tid >> 5;
    const int lane = tid & 31;
    const int cta = blockIdx.x;
    const uint32_t sb = smem_u32(smem);

    // ---- shared staging (all 576 threads) ----
    for (int i = tid; i < 9 * NCT * 8; i += 576) {
        int r = i >> 3, j = i & 7;
        *(uint4*)(smem + SM_B + r * ROWB + j * 16) = ((const uint4*)(g_bs8 + (size_t)r * 128))[j];
    }
    {
        const uint4* gw = (const uint4*)g_wbits;
        for (int i = tid; i < NCS * 9; i += 576)
            ((uint4*)(smem + SM_W))[i] = gw[NCT * 9 + i];
    }
    for (int i = tid; i < 3 * NCS; i += 576) {
        int cl = i / NCS, co = NCT + (i - cl * NCS);
        float A = g_A[co], Bv = g_Bc[co];
        float wc[9];
#pragma unroll
        for (int t = 0; t < 9; t++) wc[t] = g_wcnt[co * 9 + t];
        float cr = (cl == 0 ? wc[0] + wc[1] + wc[2] : 0.0f)
                 + (cl == 2 ? wc[6] + wc[7] + wc[8] : 0.0f);
        float c0 = (cl == 0 ? 0.0f : wc[0]) + wc[3] + (cl == 2 ? 0.0f : wc[6]);
        float c2 = (cl == 0 ? 0.0f : wc[2]) + wc[5] + (cl == 2 ? 0.0f : wc[8]);
        ((float4*)(smem + SM_CC))[i] = make_float4(-2.0f * A, A, fmaf(2.0f * A, cr, Bv), 2.0f * A * c0);
        ((float*)(smem + SM_Q2))[i] = 2.0f * A * c2;
    }
    if (tid < NCT) {
        ((float*)(smem + SM_ABN))[tid] = g_A[tid];
        ((float*)(smem + SM_ABN))[NCT + tid] = g_Bc[tid];
    }
    __syncthreads();

    if (warp < 4) {
        // ================= TENSOR GROUP: 4 warps, co 0..39 =================
        const int g = lane >> 2, tg = lane & 3;
        const int m0 = warp * 32;
        const int t0 = (int)(((long)cta * NTT) / GRID_CONV);
        const int t1 = (int)(((long)(cta + 1) * NTT) / GRID_CONV);
        const uint32_t aAddr = sb + SM_A + (uint32_t)(m0 + g) * ROWB + tg * 8;
        const uint32_t bAddr = sb + SM_B + (uint32_t)g * ROWB + tg * 8;
        const float* abn = (const float*)(smem + SM_ABN);

        for (int t = t0; t < t1; t++) {
            int img = t / TPI, tt = t - img * TPI;
            size_t row0 = (size_t)GUARD + (size_t)img * IMG_ROWS + (size_t)tt * 128 - 59;
            for (int i = tid; i < 246 * 8; i += 128) {
                int r = i >> 3, j = i & 7;
                *(uint4*)(smem + SM_A + r * ROWB + j * 16) =
                    ((const uint4*)(g_spad + (row0 + r) * 128))[j];
            }
            asm volatile("bar.sync 1, 128;" ::: "memory");

            int c[2][5][4];
#pragma unroll
            for (int mi = 0; mi < 2; mi++)
#pragma unroll
                for (int ni = 0; ni < 5; ni++)
#pragma unroll
                    for (int r = 0; r < 4; r++) c[mi][ni][r] = 0;

            for (int tap = 0; tap < 9; tap++) {
                const uint32_t at = aAddr + (uint32_t)((tap / 3) * 58 + (tap % 3)) * ROWB;
                const uint32_t bt = bAddr + (uint32_t)(tap * NCT) * ROWB;
#pragma unroll
                for (int ks = 0; ks < 4; ks++) {
                    uint32_t a[2][4];
#pragma unroll
                    for (int mi = 0; mi < 2; mi++) {
                        uint32_t lo = at + mi * (16 * ROWB) + ks * 32;
                        asm volatile("ld.shared.v2.b32 {%0,%1}, [%2];"
                                     : "=r"(a[mi][0]), "=r"(a[mi][2]) : "r"(lo));
                        asm volatile("ld.shared.v2.b32 {%0,%1}, [%2];"
                                     : "=r"(a[mi][1]), "=r"(a[mi][3]) : "r"(lo + 8 * ROWB));
                    }
#pragma unroll
                    for (int ni = 0; ni < 5; ni++) {
                        uint32_t b0, b1;
                        asm volatile("ld.shared.v2.b32 {%0,%1}, [%2];"
                                     : "=r"(b0), "=r"(b1) : "r"(bt + ni * (8 * ROWB) + ks * 32));
#pragma unroll
                        for (int mi = 0; mi < 2; mi++) {
                            asm volatile(
                                "mma.sync.aligned.m16n8k32.row.col.s32.s8.s8.s32 "
                                "{%0,%1,%2,%3}, {%4,%5,%6,%7}, {%8,%9}, {%0,%1,%2,%3};"
                                : "+r"(c[mi][ni][0]), "+r"(c[mi][ni][1]),
                                  "+r"(c[mi][ni][2]), "+r"(c[mi][ni][3])
                                : "r"(a[mi][0]), "r"(a[mi][1]), "r"(a[mi][2]), "r"(a[mi][3]),
                                  "r"(b0), "r"(b1));
                        }
                    }
                }
            }
            size_t base = (size_t)img * C * HW;
#pragma unroll
            for (int mi = 0; mi < 2; mi++) {
#pragma unroll
                for (int half = 0; half < 2; half++) {
                    int row = m0 + mi * 16 + half * 8 + g;
                    int pos = tt * 128 + row;
                    int prow = pos / PROW, pcol = pos - prow * PROW;
                    if (pos < PIMG && prow >= 1 && prow <= 56 && pcol >= 1 && pcol <= 56) {
                        size_t off = base + (size_t)(prow - 1) * W + (pcol - 1);
#pragma unroll
                        for (int ni = 0; ni < 5; ni++) {
                            int co = ni * 8 + tg * 2;
                            size_t o0 = off + (size_t)co * HW;
                            float r0 = __ldg(x + o0), r1 = __ldg(x + o0 + HW);
                            out[o0] = fmaf((float)c[mi][ni][half * 2], abn[co], abn[NCT + co]) + r0;
                            out[o0 + HW] = fmaf((float)c[mi][ni][half * 2 + 1], abn[co + 1], abn[NCT + co + 1]) + r1;
                        }
                    }
                }
            }
            asm volatile("bar.sync 1, 128;" ::: "memory");
        }
    } else {
        // ================= SCALAR GROUP: 14 warps (448 lanes), co 40..127 =================
        // lane l: chunk = l/112 (22 co), pos = l%112: rowsel = pos/56, w = pos%56.
        const int sl = tid - 128;               // 0..447
        const int chunk = sl / 112;             // 0..3
        const int pos = sl - chunk * 112;
        const int rowsel = pos / 56;
        const int w = pos - rowsel * 56;
        const int co0 = NCT + chunk * 22;

        const int p0 = (int)(((long)cta * NPAIR) / GRID_CONV);
        const int p1 = (int)(((long)(cta + 1) * NPAIR) / GRID_CONV);
        uint4* s_x = (uint4*)(smem + SM_X);
        const uint4* s_w = (const uint4*)(smem + SM_W);
        const float4* s_cc = (const float4*)(smem + SM_CC);
        const float* s_q2 = (const float*)(smem + SM_Q2);

        float q0f = (w == 0) ? 1.0f : 0.0f;
        float q2f = (w == 55) ? 1.0f : 0.0f;

        for (int p = p0; p < p1; p++) {
            int img = p / 28, pr = p - img * 28;
            int hbase = pr * 2;
            asm volatile("bar.sync 2, 448;" ::: "memory");
            for (int i = sl; i < 4 * 58; i += 448) {
                int r = i / 58, cw = i - r * 58 - 1;
                int hr = hbase - 1 + r;
                uint4 v = make_uint4(0u, 0u, 0u, 0u);
                if (hr >= 0 && hr < 56 && cw >= 0 && cw < 56)
                    v = g_xbits[(size_t)img * HW + hr * W + cw];
                s_x[i] = v;
            }
            asm volatile("bar.sync 2, 448;" ::: "memory");

            int h = hbase + rowsel;
            int cl = (h == 0) ? 0 : ((h == 55) ? 2 : 1);
            float vr = 3.0f - (cl == 0 ? 1.0f : 0.0f) - (cl == 2 ? 1.0f : 0.0f);
            float nv128 = 128.0f * vr * (3.0f - q0f - q2f);

            uint4 xv[9];
#pragma unroll
            for (int t = 0; t < 9; t++)
                xv[t] = s_x[(rowsel + t / 3) * 58 + w + (t % 3)];

            const float* resid = x + (size_t)img * C * HW + (size_t)h * W + w;
            float* outp = out + (size_t)img * C * HW + (size_t)h * W + w;

#pragma unroll 2
            for (int k = 0; k < 22; k++) {
                int co = co0 + k;
                int ic = co - NCT;
                float r = resid[(size_t)co * HW];
                float4 cf = s_cc[cl * NCS + ic];
                float q2v = s_q2[cl * NCS + ic];
                int acc1 = 0, acc2 = 0;
#pragma unroll
                for (int g2 = 0; g2 < 3; g2++) {
                    uint4 wv0 = s_w[ic * 9 + 3 * g2 + 0];
                    uint4 wv1 = s_w[ic * 9 + 3 * g2 + 1];
                    uint4 wv2 = s_w[ic * 9 + 3 * g2 + 2];
                    uint32_t s0, c0, s1, c1, s2, c2, s3, c3;
                    fadd(xv[3*g2].x ^ wv0.x, xv[3*g2+1].x ^ wv1.x, xv[3*g2+2].x ^ wv2.x, s0, c0);
                    fadd(xv[3*g2].y ^ wv0.y, xv[3*g2+1].y ^ wv1.y, xv[3*g2+2].y ^ wv2.y, s1, c1);
                    fadd(xv[3*g2].z ^ wv0.z, xv[3*g2+1].z ^ wv1.z, xv[3*g2+2].z ^ wv2.z, s2, c2);
                    fadd(xv[3*g2].w ^ wv0.w, xv[3*g2+1].w ^ wv1.w, xv[3*g2+2].w ^ wv2.w, s3, c3);
                    acc1 += __popc(s0) + __popc(s1) + __popc(s2) + __popc(s3);
                    acc2 += __popc(c0) + __popc(c1) + __popc(c2) + __popc(c3);
                }
                int acc = acc1 + 2 * acc2;
                float K = fmaf(cf.y, nv128, cf.z);
                K = fmaf(q0f, cf.w, K);
                K = fmaf(q2f, q2v, K);
                outp[(size_t)co * HW] = fmaf(cf.x, (float)acc, K) + r;
            }
        }
    }
}

// ---------------------------------------------------------------------------
extern "C" void kernel_launch(void* const* d_in, const int* in_sizes, int n_in,
                              void* d_out, int out_size) {
    const float* x     = (const float*)d_in[0];
    const float* wgt   = (const float*)d_in[1];
    const float* gamma = (const float*)d_in[2];
    const float* beta  = (const float*)d_in[3];
    const float* mean  = (const float*)d_in[4];
    const float* var   = (const float*)d_in[5];
    float* out = (float*)d_out;
    (void)in_sizes; (void)n_in; (void)out_size;

    cudaFuncSetAttribute(conv_kernel, cudaFuncAttributeMaxDynamicSharedMemorySize, SMEM_TOTAL);

    sign_kernel<<<NB * H, 256>>>(x);
    wprep_kernel<<<C, 128>>>(wgt, gamma, beta, mean, var);
    conv_kernel<<<GRID_CONV, 576, SMEM_TOTAL>>>(x, out);
}

// round 11
// speedup vs baseline: 2.3312x; 1.1020x over previous
#include <cuda_runtime.h>
#include <cstdint>

#define NB 64
#define C  128
#define H  56
#define W  56
#define HW 3136
#define PROW 58
#define PIMG 3364
#define IMG_ROWS 3584
#define GUARD 128
#define TOT_ROWS (GUARD + NB*IMG_ROWS)
#define TPI 27
#define NTT (NB*TPI)                  // 1728 tensor tiles
#define NPAIR (NB*28)                 // 1792 scalar row-pairs
#define GRID_CONV 148
#define ROWB 144
#define NCT 40                        // tensor co count (co 0..39)
#define NCS 88                        // scalar co count (co 40..127)

// smem offsets (bytes)
#define SM_B    0                     // 9*40*ROWB = 51840
#define ABUF    35424                 // one A buffer: 246*ROWB
#define SM_A    51840                 // 2 buffers = 70848
#define SM_W    122688                // 88*9*16 = 12672
#define XBUF    3712                  // one X buffer: 4*58*16
#define SM_X    135360                // 2 buffers = 7424
#define SM_CC   142784                // 3*88*16 = 4224
#define SM_Q2   147008                // 3*88*4 = 1056
#define SM_ABN  148064                // 40*2*4 = 320
#define SMEM_TOTAL 148384

// NOTE: no zero_kernel — static __device__ globals are zero-initialized at
// module load, and interior writes below never touch pad/guard/tail rows.
__device__ __align__(1024) unsigned char g_spad[(size_t)TOT_ROWS * 128]; // s8 signs, k-permuted
__device__ __align__(16)   unsigned char g_bs8[9 * NCT * 128];           // [tap][co<40][ci'] s8
__device__ __align__(16)   uint32_t g_wbits[C * 9 * 4];                  // bitmask [co][tap][word]
__device__ float g_A[C], g_Bc[C], g_wcnt[C * 9];
__device__ uint4 g_xbits[NB * HW];

__host__ __device__ __forceinline__ int permw(int w) {
    int ww = w & 7;
    return (w & ~7) | ((ww < 4) ? (ww << 1) : (((ww - 4) << 1) | 1));
}
__device__ __forceinline__ uint32_t smem_u32(const void* p) {
    uint32_t a;
    asm("{ .reg .u64 t; cvta.to.shared.u64 t, %1; cvt.u32.u64 %0, t; }" : "=r"(a) : "l"(p));
    return a;
}
__device__ __forceinline__ void fadd(uint32_t a, uint32_t b, uint32_t c,
                                     uint32_t& s, uint32_t& cy) {
    s = a ^ b ^ c; cy = (a & b) | (c & (a ^ b));
}
__device__ __forceinline__ void cpa16(uint32_t d, const void* s) {
    asm volatile("cp.async.cg.shared.global [%0], [%1], 16;" :: "r"(d), "l"(s));
}
__device__ __forceinline__ void cpa16z(uint32_t d, const void* s, int sz) {
    asm volatile("cp.async.cg.shared.global [%0], [%1], 16, %2;" :: "r"(d), "l"(s), "r"(sz));
}
#define CPA_COMMIT() asm volatile("cp.async.commit_group;" ::: "memory")
#define CPA_WAIT1()  asm volatile("cp.async.wait_group 1;" ::: "memory")
#define CPA_WAIT0()  asm volatile("cp.async.wait_group 0;" ::: "memory")

// ---------------- Kernel 1: x -> s8 spad (permuted) + bitpacked xbits ----------------
__global__ void sign_kernel(const float* __restrict__ x) {
    __shared__ uint32_t s[56][33];
    int nb = blockIdx.x;
    int n = nb / H, h = nb - n * H;
    int t = threadIdx.x;
    const float* xp = x + (size_t)n * C * HW + (size_t)h * W;
    for (int it = t; it < 56 * 32; it += 256) {
        int w = it % 56, cg = it / 56;
        uint32_t b = 0;
#pragma unroll
        for (int j = 0; j < 4; j++) {
            float v = __ldg(xp + (size_t)(cg * 4 + j) * HW + w);
            b |= ((v < 0.0f) ? 0xFFu : 0x01u) << (j * 8);
        }
        s[w][cg] = b;
    }
    __syncthreads();
    uint32_t* dst = (uint32_t*)(g_spad +
        ((size_t)GUARD + (size_t)n * IMG_ROWS + (size_t)(h + 1) * PROW + 1) * 128);
    for (int it = t; it < 56 * 32; it += 256) {
        int pix = it >> 5, l = it & 31;
        dst[(size_t)pix * 32 + permw(l)] = s[pix][l];
    }
    if (t < 224) {
        int w = t >> 2, j = t & 3;
        uint32_t b = 0;
#pragma unroll
        for (int m = 0; m < 8; m++) {
            uint32_t sv = s[w][j * 8 + m];
#pragma unroll
            for (int k = 0; k < 4; k++)
                b |= ((sv >> (8 * k + 7)) & 1u) << (m * 4 + k);
        }
        ((uint32_t*)&g_xbits[(size_t)n * HW + h * W + w])[j] = b;
    }
}

// ---------------- Kernel 2: parallel weight prep (grid = 128 co, 128 thr) ----------------
__global__ void wprep_kernel(const float* __restrict__ wgt,
                             const float* __restrict__ gamma,
                             const float* __restrict__ beta,
                             const float* __restrict__ mean,
                             const float* __restrict__ var) {
    __shared__ float s_abs[4];
    __shared__ int   s_pc[9][4];
    int co = blockIdx.x;
    int t  = threadIdx.x;          // = ci
    int lane = t & 31, j = t >> 5;

    float v[9];
    const float* wp = wgt + (size_t)co * 1152 + (size_t)t * 9;
    float sabs = 0.0f;
#pragma unroll
    for (int tap = 0; tap < 9; tap++) { v[tap] = wp[tap]; sabs += fabsf(v[tap]); }
#pragma unroll
    for (int o = 16; o > 0; o >>= 1) sabs += __shfl_xor_sync(0xffffffffu, sabs, o);
    if (lane == 0) s_abs[j] = sabs;

    int pci = permw(t >> 2) * 4 + (t & 3);
#pragma unroll
    for (int tap = 0; tap < 9; tap++) {
        uint32_t wb = __ballot_sync(0xffffffffu, v[tap] < 0.0f);
        if (lane == 0) {
            g_wbits[(co * 9 + tap) * 4 + j] = wb;
            s_pc[tap][j] = __popc(wb);
        }
        if (co < NCT)
            g_bs8[((size_t)tap * NCT + co) * 128 + pci] = (v[tap] < 0.0f) ? 0xFF : 0x01;
    }
    __syncthreads();
    if (t < 9)
        g_wcnt[co * 9 + t] = (float)(s_pc[t][0] + s_pc[t][1] + s_pc[t][2] + s_pc[t][3]);
    if (t == 0) {
        float tot = s_abs[0] + s_abs[1] + s_abs[2] + s_abs[3];
        float scale = tot * (1.0f / 1152.0f);
        float inv = gamma[co] * rsqrtf(var[co] + 1e-5f);
        g_A[co]  = scale * inv;
        g_Bc[co] = beta[co] - mean[co] * inv;
    }
}

// ---------------- Kernel 3: hybrid conv, cp.async double-buffered staging ----------------
// 576 threads: warps 0-3 tensor (mma.sync, co 0..39), warps 4-17 scalar (CSA, co 40..127).
__global__ void __launch_bounds__(576, 1)
conv_kernel(const float* __restrict__ x, float* __restrict__ out) {
    extern __shared__ unsigned char smem[];
    const int tid = threadIdx.x;
    const int warp = tid >> 5;
    const int lane = tid & 31;
    const int cta = blockIdx.x;
    const uint32_t sb = smem_u32(smem);

    // ---- shared staging (all 576 threads) ----
    for (int i = tid; i < 9 * NCT * 8; i += 576) {
        int r = i >> 3, j = i & 7;
        *(uint4*)(smem + SM_B + r * ROWB + j * 16) = ((const uint4*)(g_bs8 + (size_t)r * 128))[j];
    }
    {
        const uint4* gw = (const uint4*)g_wbits;
        for (int i = tid; i < NCS * 9; i += 576)
            ((uint4*)(smem + SM_W))[i] = gw[NCT * 9 + i];
    }
    for (int i = tid; i < 3 * NCS; i += 576) {
        int cl = i / NCS, co = NCT + (i - cl * NCS);
        float A = g_A[co], Bv = g_Bc[co];
        float wc[9];
#pragma unroll
        for (int t = 0; t < 9; t++) wc[t] = g_wcnt[co * 9 + t];
        float cr = (cl == 0 ? wc[0] + wc[1] + wc[2] : 0.0f)
                 + (cl == 2 ? wc[6] + wc[7] + wc[8] : 0.0f);
        float c0 = (cl == 0 ? 0.0f : wc[0]) + wc[3] + (cl == 2 ? 0.0f : wc[6]);
        float c2 = (cl == 0 ? 0.0f : wc[2]) + wc[5] + (cl == 2 ? 0.0f : wc[8]);
        ((float4*)(smem + SM_CC))[i] = make_float4(-2.0f * A, A, fmaf(2.0f * A, cr, Bv), 2.0f * A * c0);
        ((float*)(smem + SM_Q2))[i] = 2.0f * A * c2;
    }
    if (tid < NCT) {
        ((float*)(smem + SM_ABN))[tid] = g_A[tid];
        ((float*)(smem + SM_ABN))[NCT + tid] = g_Bc[tid];
    }
    __syncthreads();

    if (warp < 4) {
        // ================= TENSOR GROUP: 4 warps, co 0..39 =================
        const int g = lane >> 2, tg = lane & 3;
        const int m0 = warp * 32;
        const int t0 = (int)(((long)cta * NTT) / GRID_CONV);
        const int t1 = (int)(((long)(cta + 1) * NTT) / GRID_CONV);
        const float* abn = (const float*)(smem + SM_ABN);
        const uint32_t bAddr = sb + SM_B + (uint32_t)g * ROWB + tg * 8;

        // async A staging: tile t -> buffer bi
        auto stageA = [&](int t, int bi) {
            int img = t / TPI, tt = t - img * TPI;
            size_t row0 = (size_t)GUARD + (size_t)img * IMG_ROWS + (size_t)tt * 128 - 59;
            uint32_t dst0 = sb + SM_A + (uint32_t)bi * ABUF;
            for (int i = tid; i < 246 * 8; i += 128) {
                int r = i >> 3, j = i & 7;
                cpa16(dst0 + r * ROWB + j * 16, g_spad + (row0 + r) * 128 + j * 16);
            }
        };

        if (t0 < t1) stageA(t0, 0);
        CPA_COMMIT();

        for (int t = t0; t < t1; t++) {
            int bi = (t - t0) & 1;
            if (t + 1 < t1) { stageA(t + 1, bi ^ 1); CPA_COMMIT(); CPA_WAIT1(); }
            else            { CPA_WAIT0(); }
            asm volatile("bar.sync 1, 128;" ::: "memory");

            const uint32_t aAddr = sb + SM_A + (uint32_t)bi * ABUF
                                 + (uint32_t)(m0 + g) * ROWB + tg * 8;
            int img = t / TPI, tt = t - img * TPI;

            int c[2][5][4];
#pragma unroll
            for (int mi = 0; mi < 2; mi++)
#pragma unroll
                for (int ni = 0; ni < 5; ni++)
#pragma unroll
                    for (int r = 0; r < 4; r++) c[mi][ni][r] = 0;

            for (int tap = 0; tap < 9; tap++) {
                const uint32_t at = aAddr + (uint32_t)((tap / 3) * 58 + (tap % 3)) * ROWB;
                const uint32_t bt = bAddr + (uint32_t)(tap * NCT) * ROWB;
#pragma unroll
                for (int ks = 0; ks < 4; ks++) {
                    uint32_t a[2][4];
#pragma unroll
                    for (int mi = 0; mi < 2; mi++) {
                        uint32_t lo = at + mi * (16 * ROWB) + ks * 32;
                        asm volatile("ld.shared.v2.b32 {%0,%1}, [%2];"
                                     : "=r"(a[mi][0]), "=r"(a[mi][2]) : "r"(lo));
                        asm volatile("ld.shared.v2.b32 {%0,%1}, [%2];"
                                     : "=r"(a[mi][1]), "=r"(a[mi][3]) : "r"(lo + 8 * ROWB));
                    }
#pragma unroll
                    for (int ni = 0; ni < 5; ni++) {
                        uint32_t b0, b1;
                        asm volatile("ld.shared.v2.b32 {%0,%1}, [%2];"
                                     : "=r"(b0), "=r"(b1) : "r"(bt + ni * (8 * ROWB) + ks * 32));
#pragma unroll
                        for (int mi = 0; mi < 2; mi++) {
                            asm volatile(
                                "mma.sync.aligned.m16n8k32.row.col.s32.s8.s8.s32 "
                                "{%0,%1,%2,%3}, {%4,%5,%6,%7}, {%8,%9}, {%0,%1,%2,%3};"
                                : "+r"(c[mi][ni][0]), "+r"(c[mi][ni][1]),
                                  "+r"(c[mi][ni][2]), "+r"(c[mi][ni][3])
                                : "r"(a[mi][0]), "r"(a[mi][1]), "r"(a[mi][2]), "r"(a[mi][3]),
                                  "r"(b0), "r"(b1));
                        }
                    }
                }
            }
            size_t base = (size_t)img * C * HW;
#pragma unroll
            for (int mi = 0; mi < 2; mi++) {
#pragma unroll
                for (int half = 0; half < 2; half++) {
                    int row = m0 + mi * 16 + half * 8 + g;
                    int pos = tt * 128 + row;
                    int prow = pos / PROW, pcol = pos - prow * PROW;
                    if (pos < PIMG && prow >= 1 && prow <= 56 && pcol >= 1 && pcol <= 56) {
                        size_t off = base + (size_t)(prow - 1) * W + (pcol - 1);
#pragma unroll
                        for (int ni = 0; ni < 5; ni++) {
                            int co = ni * 8 + tg * 2;
                            size_t o0 = off + (size_t)co * HW;
                            float r0 = __ldg(x + o0), r1 = __ldg(x + o0 + HW);
                            out[o0] = fmaf((float)c[mi][ni][half * 2], abn[co], abn[NCT + co]) + r0;
                            out[o0 + HW] = fmaf((float)c[mi][ni][half * 2 + 1], abn[co + 1], abn[NCT + co + 1]) + r1;
                        }
                    }
                }
            }
            asm volatile("bar.sync 1, 128;" ::: "memory");
        }
    } else {
        // ================= SCALAR GROUP: 14 warps (448 lanes), co 40..127 =================
        const int sl = tid - 128;               // 0..447
        const int chunk = sl / 112;             // 0..3 -> 22 co each
        const int pos = sl - chunk * 112;
        const int rowsel = pos / 56;
        const int w = pos - rowsel * 56;
        const int co0 = NCT + chunk * 22;

        const int p0 = (int)(((long)cta * NPAIR) / GRID_CONV);
        const int p1 = (int)(((long)(cta + 1) * NPAIR) / GRID_CONV);
        const uint4* s_w = (const uint4*)(smem + SM_W);
        const float4* s_cc = (const float4*)(smem + SM_CC);
        const float* s_q2 = (const float*)(smem + SM_Q2);

        float q0f = (w == 0) ? 1.0f : 0.0f;
        float q2f = (w == 55) ? 1.0f : 0.0f;

        // async x staging: pair p -> buffer bi (rows hbase-1 .. hbase+2, zero-padded)
        auto stageX = [&](int p, int bi) {
            int img = p / 28, pr = p - img * 28;
            int hbase = pr * 2;
            uint32_t dst0 = sb + SM_X + (uint32_t)bi * XBUF;
            for (int i = sl; i < 4 * 58; i += 448) {
                int r = i / 58, cw = i - r * 58 - 1;
                int hr = hbase - 1 + r;
                bool ok = (hr >= 0 && hr < 56 && cw >= 0 && cw < 56);
                int hc = ok ? hr : 0, wc2 = ok ? cw : 0;
                cpa16z(dst0 + i * 16,
                       &g_xbits[(size_t)img * HW + hc * W + wc2], ok ? 16 : 0);
            }
        };

        if (p0 < p1) stageX(p0, 0);
        CPA_COMMIT();

        for (int p = p0; p < p1; p++) {
            int bi = (p - p0) & 1;
            if (p + 1 < p1) { stageX(p + 1, bi ^ 1); CPA_COMMIT(); CPA_WAIT1(); }
            else            { CPA_WAIT0(); }
            asm volatile("bar.sync 2, 448;" ::: "memory");

            const uint4* s_x = (const uint4*)(smem + SM_X + bi * XBUF);
            int img = p / 28, pr = p - img * 28;
            int h = pr * 2 + rowsel;
            int cl = (h == 0) ? 0 : ((h == 55) ? 2 : 1);
            float vr = 3.0f - (cl == 0 ? 1.0f : 0.0f) - (cl == 2 ? 1.0f : 0.0f);
            float nv128 = 128.0f * vr * (3.0f - q0f - q2f);

            uint4 xv[9];
#pragma unroll
            for (int t = 0; t < 9; t++)
                xv[t] = s_x[(rowsel + t / 3) * 58 + w + (t % 3)];

            const float* resid = x + (size_t)img * C * HW + (size_t)h * W + w;
            float* outp = out + (size_t)img * C * HW + (size_t)h * W + w;

#pragma unroll 2
            for (int k = 0; k < 22; k++) {
                int co = co0 + k;
                int ic = co - NCT;
                float r = resid[(size_t)co * HW];
                float4 cf = s_cc[cl * NCS + ic];
                float q2v = s_q2[cl * NCS + ic];
                int acc1 = 0, acc2 = 0;
#pragma unroll
                for (int g2 = 0; g2 < 3; g2++) {
                    uint4 wv0 = s_w[ic * 9 + 3 * g2 + 0];
                    uint4 wv1 = s_w[ic * 9 + 3 * g2 + 1];
                    uint4 wv2 = s_w[ic * 9 + 3 * g2 + 2];
                    uint32_t s0, c0, s1, c1, s2, c2, s3, c3;
                    fadd(xv[3*g2].x ^ wv0.x, xv[3*g2+1].x ^ wv1.x, xv[3*g2+2].x ^ wv2.x, s0, c0);
                    fadd(xv[3*g2].y ^ wv0.y, xv[3*g2+1].y ^ wv1.y, xv[3*g2+2].y ^ wv2.y, s1, c1);
                    fadd(xv[3*g2].z ^ wv0.z, xv[3*g2+1].z ^ wv1.z, xv[3*g2+2].z ^ wv2.z, s2, c2);
                    fadd(xv[3*g2].w ^ wv0.w, xv[3*g2+1].w ^ wv1.w, xv[3*g2+2].w ^ wv2.w, s3, c3);
                    acc1 += __popc(s0) + __popc(s1) + __popc(s2) + __popc(s3);
                    acc2 += __popc(c0) + __popc(c1) + __popc(c2) + __popc(c3);
                }
                int acc = acc1 + 2 * acc2;
                float K = fmaf(cf.y, nv128, cf.z);
                K = fmaf(q0f, cf.w, K);
                K = fmaf(q2f, q2v, K);
                outp[(size_t)co * HW] = fmaf(cf.x, (float)acc, K) + r;
            }
            asm volatile("bar.sync 2, 448;" ::: "memory");
        }
    }
}

// ---------------------------------------------------------------------------
extern "C" void kernel_launch(void* const* d_in, const int* in_sizes, int n_in,
                              void* d_out, int out_size) {
    const float* x     = (const float*)d_in[0];
    const float* wgt   = (const float*)d_in[1];
    const float* gamma = (const float*)d_in[2];
    const float* beta  = (const float*)d_in[3];
    const float* mean  = (const float*)d_in[4];
    const float* var   = (const float*)d_in[5];
    float* out = (float*)d_out;
    (void)in_sizes; (void)n_in; (void)out_size;

    cudaFuncSetAttribute(conv_kernel, cudaFuncAttributeMaxDynamicSharedMemorySize, SMEM_TOTAL);

    sign_kernel<<<NB * H, 256>>>(x);
    wprep_kernel<<<C, 128>>>(wgt, gamma, beta, mean, var);
    conv_kernel<<<GRID_CONV, 576, SMEM_TOTAL>>>(x, out);
}